// round 5
// baseline (speedup 1.0000x reference)
#include <cuda_runtime.h>
#include <cuda_fp16.h>
#include <cstdint>

#define NN  100000
#define NE  1600000
#define NG  512
#define LL  1000
#define FXD 4
#define FXT 5
#define H   64
#define H2  128
#define NOUT 2

// ---------------- scratch ----------------
__device__ float  d_deg[NN];
__device__ float  d_dis[NN];
__device__ float4 d_aggx[NN];          // [N,4] aggregated raw x
__device__ float4 d_h1[NN * (H/4)];    // [N,64] relu layer-1 output (fp32)
__device__ __half d_h1h[NN * H];       // [N,64] fp16 copy for gather
__device__ float4 d_aggh[NN * (H/4)];  // [N,64] aggregated h1
__device__ int    d_gbits[NG * H2];    // pooled max(h2) as ordered int bits
__device__ float  d_tmax[NG * H];      // conv1d branch pooled output

__device__ __forceinline__ void red_add4(float4* p, float4 v) {
    unsigned long long gp = (unsigned long long)__cvta_generic_to_global(p);
    asm volatile("red.global.add.v4.f32 [%0], {%1,%2,%3,%4};"
                 :: "l"(gp), "f"(v.x), "f"(v.y), "f"(v.z), "f"(v.w) : "memory");
}
__device__ __forceinline__ unsigned long long fma2(unsigned long long a,
                                                   unsigned long long b,
                                                   unsigned long long c) {
    unsigned long long d;
    asm("fma.rn.f32x2 %0, %1, %2, %3;" : "=l"(d) : "l"(a), "l"(b), "l"(c));
    return d;
}
__device__ __forceinline__ unsigned long long pack2(float a, float b) {
    unsigned long long d;
    asm("mov.b64 %0, {%1,%2};" : "=l"(d) : "f"(a), "f"(b));
    return d;
}
__device__ __forceinline__ float2 unpack2(unsigned long long a) {
    float2 r;
    asm("mov.b64 {%0,%1}, %2;" : "=f"(r.x), "=f"(r.y) : "l"(a));
    return r;
}

// ---------------- K0: init scratch ----------------
__global__ void k_init() {
    int stride = gridDim.x * blockDim.x;
    int tid = blockIdx.x * blockDim.x + threadIdx.x;
    float4 z4 = make_float4(0.f, 0.f, 0.f, 0.f);
    for (int i = tid; i < NN * (H/4); i += stride) d_aggh[i] = z4;
    for (int i = tid; i < NN; i += stride) { d_aggx[i] = z4; d_deg[i] = 1.0f; } // self-loop deg
    for (int i = tid; i < NG * H2; i += stride) d_gbits[i] = 0;                 // relu>=0
}

// ---------------- K1: degree ----------------
__global__ void k_deg(const int* __restrict__ ei) {
    int e = blockIdx.x * blockDim.x + threadIdx.x;
    if (e < NE) atomicAdd(&d_deg[ei[NE + e]], 1.0f);
}

// ---------------- K2: dis = rsqrt(deg) ----------------
__global__ void k_dis() {
    int i = blockIdx.x * blockDim.x + threadIdx.x;
    if (i < NN) d_dis[i] = rsqrtf(d_deg[i]);
}

// ---------------- K3: layer-1 raw-x scatter ----------------
__global__ void k_prep(const int* __restrict__ ei, const float* __restrict__ x) {
    int e = blockIdx.x * blockDim.x + threadIdx.x;
    if (e >= NE) return;
    int r = ei[e];
    int c = ei[NE + e];
    float w = d_dis[r] * d_dis[c];
    float4 xv = ((const float4*)x)[r];
    xv.x *= w; xv.y *= w; xv.z *= w; xv.w *= w;
    red_add4(&d_aggx[c], xv);
}

// ---------------- K4: h1 = relu((aggx + dis^2 * x) @ W1 + b1), fp32 + fp16 ----------------
__global__ void k_h1(const float* __restrict__ x,
                     const float* __restrict__ W1, const float* __restrict__ b1) {
    int gid = blockIdx.x * blockDim.x + threadIdx.x;  // N*64 threads
    if (gid >= NN * H) return;
    int i = gid >> 6;
    int f = gid & 63;
    float4 a = d_aggx[i];
    float4 xv = ((const float4*)x)[i];
    float s = d_dis[i] * d_dis[i];
    a.x += s * xv.x; a.y += s * xv.y; a.z += s * xv.z; a.w += s * xv.w;
    float h = b1[f] + a.x * W1[f] + a.y * W1[H + f] + a.z * W1[2*H + f] + a.w * W1[3*H + f];
    h = fmaxf(h, 0.f);
    ((float*)d_h1)[gid] = h;
    d_h1h[gid] = __float2half_rn(h);
}

// ---------------- K5: layer-2 scatter: aggh[c] += w * h1[r] (8 threads/edge, fp16 gather) ----
__global__ void k_scatter(const int* __restrict__ ei) {
    int gid = blockIdx.x * blockDim.x + threadIdx.x;  // NE*8 threads
    if (gid >= NE * 8) return;
    int e  = gid >> 3;
    int ch = gid & 7;
    int r = ei[e];
    int c = ei[NE + e];
    float w = d_dis[r] * d_dis[c];
    uint4 hv = *(const uint4*)(d_h1h + r * H + ch * 8);   // 8 halves
    const __half2* hp = (const __half2*)&hv;
    float2 f0 = __half22float2(hp[0]);
    float2 f1 = __half22float2(hp[1]);
    float2 f2 = __half22float2(hp[2]);
    float2 f3 = __half22float2(hp[3]);
    float4 v0 = make_float4(f0.x * w, f0.y * w, f1.x * w, f1.y * w);
    float4 v1 = make_float4(f2.x * w, f2.y * w, f3.x * w, f3.y * w);
    red_add4(&d_aggh[c * 16 + ch * 2],     v0);
    red_add4(&d_aggh[c * 16 + ch * 2 + 1], v1);
}

// ---------------- K6: h2 = relu((aggh + dis^2*h1) @ W2 + b2), fused max-pool ----------------
// 8 nodes per block, 128 threads (one per output feature), packed f32x2 math.
__global__ void k_h2pool(const float* __restrict__ W2, const float* __restrict__ b2,
                         const int* __restrict__ batch) {
    __shared__ __align__(16) float vt[H][12];   // [k][node], nodes 0..7, padded row
    int i0 = blockIdx.x * 8;                    // 12500 blocks
    int tid = threadIdx.x;                      // 128 threads
    const float* agghf = (const float*)d_aggh;
    const float* h1f   = (const float*)d_h1;
    for (int idx = tid; idx < 8 * H; idx += 128) {
        int n = idx >> 6, k = idx & 63;
        int i = i0 + n;
        float s = d_dis[i] * d_dis[i];
        vt[k][n] = agghf[i * H + k] + s * h1f[i * H + k];
    }
    __syncthreads();

    int f = tid;
    float bb = b2[f];
    unsigned long long a01 = pack2(bb, bb), a23 = a01, a45 = a01, a67 = a01;
#pragma unroll
    for (int k = 0; k < H; k++) {
        float wv = W2[k * H2 + f];
        unsigned long long wd = pack2(wv, wv);
        ulonglong2 P = *(const ulonglong2*)&vt[k][0];
        ulonglong2 Q = *(const ulonglong2*)&vt[k][4];
        a01 = fma2(P.x, wd, a01);
        a23 = fma2(P.y, wd, a23);
        a45 = fma2(Q.x, wd, a45);
        a67 = fma2(Q.y, wd, a67);
    }
    float2 r01 = unpack2(a01), r23 = unpack2(a23), r45 = unpack2(a45), r67 = unpack2(a67);
    float h[8] = { r01.x, r01.y, r23.x, r23.y, r45.x, r45.y, r67.x, r67.y };

    int bA = batch[i0];
    int bB = batch[i0 + 7];
    float mA = -1.f, mB = -1.f;
#pragma unroll
    for (int n = 0; n < 8; n++) {
        float hv = fmaxf(h[n], 0.f);
        if (batch[i0 + n] == bA) mA = fmaxf(mA, hv); else mB = fmaxf(mB, hv);
    }
    atomicMax(&d_gbits[bA * H2 + f], __float_as_int(mA));
    if (bB != bA) atomicMax(&d_gbits[bB * H2 + f], __float_as_int(mB));
}

// ---------------- K7: conv1d branch (packed f32x2 over tap pairs) ----------------
__global__ void k_conv1d(const float* __restrict__ target,
                         const float* __restrict__ Wc, const float* __restrict__ bc) {
    __shared__ __align__(16) float sh[LL][6];   // 24 KB, col 5 = zero pad
    __shared__ float red[256];
    int g = blockIdx.x;
    int tid = threadIdx.x;                      // 256 threads
    const float* tg = target + (size_t)g * LL * FXT;
    for (int idx = tid; idx < LL * FXT; idx += 256) {
        int l = idx / FXT, i = idx - l * FXT;
        sh[l][i] = tg[idx];
    }
    for (int l = tid; l < LL; l += 256) sh[l][5] = 0.f;
    __syncthreads();

    int c   = tid & 63;                         // output channel
    int seg = tid >> 6;                         // 0..3 segment of L
    unsigned long long wk[3][3];
#pragma unroll
    for (int k = 0; k < 3; k++)
#pragma unroll
        for (int p = 0; p < 3; p++) {
            float w0 = Wc[c * 15 + (2 * p) * 3 + k];
            float w1 = (p < 2) ? Wc[c * 15 + (2 * p + 1) * 3 + k] : 0.f;
            wk[k][p] = pack2(w0, w1);
        }

    int start = seg * 250;
    int end = (seg == 3) ? (LL - 2) : (start + 250);  // out positions 0..997
    float m = -3.4e38f;
    for (int l = start; l < end; l++) {
        unsigned long long a0 = 0ull, a1 = 0ull, a2 = 0ull;
#pragma unroll
        for (int k = 0; k < 3; k++) {
            const unsigned long long* row = (const unsigned long long*)&sh[l + k][0];
            a0 = fma2(row[0], wk[k][0], a0);
            a1 = fma2(row[1], wk[k][1], a1);
            a2 = fma2(row[2], wk[k][2], a2);
        }
        float2 f0 = unpack2(a0), f1 = unpack2(a1), f2 = unpack2(a2);
        m = fmaxf(m, (f0.x + f0.y) + (f1.x + f1.y) + (f2.x + f2.y));
    }
    red[tid] = m;
    __syncthreads();
    if (seg == 0) {
        m = fmaxf(fmaxf(red[c], red[64 + c]), fmaxf(red[128 + c], red[192 + c]));
        m += bc[c];
        d_tmax[g * H + c] = fmaxf(m, 0.f);
    }
}

// ---------------- K8: fused final MLPs ----------------
__global__ void k_final(const float* __restrict__ Wg, const float* __restrict__ bg,
                        const float* __restrict__ Wt, const float* __restrict__ bt,
                        const float* __restrict__ Wf, const float* __restrict__ bf,
                        const float* __restrict__ Wo, const float* __restrict__ bo,
                        float* __restrict__ out) {
    __shared__ float sg[H2], st[H], sxc[H2], sy[H];
    int g = blockIdx.x;
    int f = threadIdx.x;                    // 64 threads
    sg[f]      = __int_as_float(d_gbits[g * H2 + f]);
    sg[H + f]  = __int_as_float(d_gbits[g * H2 + H + f]);
    st[f]      = d_tmax[g * H + f];
    __syncthreads();

    float gg = bg[f];
#pragma unroll 8
    for (int j = 0; j < H2; j++) gg += sg[j] * Wg[j * H + f];
    float tt = bt[f];
#pragma unroll 8
    for (int j = 0; j < H; j++) tt += st[j] * Wt[j * H + f];
    sxc[f] = gg;
    sxc[H + f] = tt;
    __syncthreads();

    float y = bf[f];
#pragma unroll 8
    for (int j = 0; j < H2; j++) y += sxc[j] * Wf[j * H + f];
    sy[f] = fmaxf(y, 0.f);
    __syncthreads();

    if (f < NOUT) {
        float o = bo[f];
#pragma unroll 8
        for (int j = 0; j < H; j++) o += sy[j] * Wo[j * NOUT + f];
        out[g * NOUT + f] = o;
    }
}

// ---------------- launch ----------------
extern "C" void kernel_launch(void* const* d_in, const int* in_sizes, int n_in,
                              void* d_out, int out_size) {
    const float* x      = (const float*)d_in[0];
    const int*   ei     = (const int*)d_in[1];
    const int*   batch  = (const int*)d_in[2];
    const float* target = (const float*)d_in[3];
    const float* W1 = (const float*)d_in[4];
    const float* b1 = (const float*)d_in[5];
    const float* W2 = (const float*)d_in[6];
    const float* b2 = (const float*)d_in[7];
    const float* Wg = (const float*)d_in[8];
    const float* bg = (const float*)d_in[9];
    const float* Wc = (const float*)d_in[10];
    const float* bc = (const float*)d_in[11];
    const float* Wt = (const float*)d_in[12];
    const float* bt = (const float*)d_in[13];
    const float* Wf = (const float*)d_in[14];
    const float* bf = (const float*)d_in[15];
    const float* Wo = (const float*)d_in[16];
    const float* bo = (const float*)d_in[17];
    float* out = (float*)d_out;

    k_init<<<4096, 256>>>();
    k_deg<<<(NE + 255) / 256, 256>>>(ei);
    k_dis<<<(NN + 255) / 256, 256>>>();
    k_prep<<<(NE + 255) / 256, 256>>>(ei, x);
    k_h1<<<(NN * H + 255) / 256, 256>>>(x, W1, b1);
    k_scatter<<<(NE * 8 + 255) / 256, 256>>>(ei);
    k_h2pool<<<NN / 8, 128>>>(W2, b2, batch);
    k_conv1d<<<NG, 256>>>(target, Wc, bc);
    k_final<<<NG, 64>>>(Wg, bg, Wt, bt, Wf, bf, Wo, bo, out);
}

// round 6
// speedup vs baseline: 1.3983x; 1.3983x over previous
#include <cuda_runtime.h>
#include <cuda_fp16.h>
#include <cstdint>

#define NN  100000
#define NE  1600000
#define NG  512
#define LL  1000
#define FXD 4
#define FXT 5
#define H   64
#define H2  128
#define NOUT 2
#define NBLK 98          // ceil(NN/1024) scan blocks

// ---------------- scratch ----------------
__device__ int    d_cnt[NN];           // in-degree (edges only; +1 self added logically)
__device__ int    d_off[NN];           // CSR offsets (incl. self)
__device__ int    d_cur[NN];           // bucket cursors
__device__ int    d_bsum[128];
__device__ int    d_bbase[128];
__device__ int    d_src[NE + NN];      // CSR source list (incl. self edge)
__device__ float  d_dis[NN];
__device__ float4 d_xs[NN];            // dis[i] * x[i]
__device__ __half d_h1s[NN * H];       // dis[i] * relu-h1[i], fp16
__device__ float  d_v[NN * H];         // layer-2 conv output (GEMM input)
__device__ int    d_gbits[NG * H2];    // pooled max(h2) as ordered int bits
__device__ float  d_tmax[NG * H];      // conv1d branch pooled output

__device__ __forceinline__ unsigned long long fma2(unsigned long long a,
                                                   unsigned long long b,
                                                   unsigned long long c) {
    unsigned long long d;
    asm("fma.rn.f32x2 %0, %1, %2, %3;" : "=l"(d) : "l"(a), "l"(b), "l"(c));
    return d;
}
__device__ __forceinline__ unsigned long long pack2(float a, float b) {
    unsigned long long d;
    asm("mov.b64 %0, {%1,%2};" : "=l"(d) : "f"(a), "f"(b));
    return d;
}
__device__ __forceinline__ float2 unpack2(unsigned long long a) {
    float2 r;
    asm("mov.b64 {%0,%1}, %2;" : "=f"(r.x), "=f"(r.y) : "l"(a));
    return r;
}

// ---------------- K0: init ----------------
__global__ void k_init() {
    int stride = gridDim.x * blockDim.x;
    int tid = blockIdx.x * blockDim.x + threadIdx.x;
    for (int i = tid; i < NN; i += stride) d_cnt[i] = 0;
    for (int i = tid; i < NG * H2; i += stride) d_gbits[i] = 0;   // relu>=0
}

// ---------------- K1: in-degree histogram ----------------
__global__ void k_hist(const int* __restrict__ ei) {
    int e = blockIdx.x * blockDim.x + threadIdx.x;
    if (e < NE) atomicAdd(&d_cnt[ei[NE + e]], 1);
}

// ---------------- K2: dis = rsqrt(deg), xs = dis*x ----------------
__global__ void k_dis_xs(const float* __restrict__ x) {
    int i = blockIdx.x * blockDim.x + threadIdx.x;
    if (i >= NN) return;
    float di = rsqrtf((float)(d_cnt[i] + 1));
    d_dis[i] = di;
    float4 xv = ((const float4*)x)[i];
    d_xs[i] = make_float4(di * xv.x, di * xv.y, di * xv.z, di * xv.w);
}

// ---------------- K3a: per-block sums of (cnt+1) ----------------
__global__ void k_scan1() {
    __shared__ int sh[256];
    int b = blockIdx.x, tid = threadIdx.x;
    int base = b * 1024 + tid * 4;
    int s = 0;
#pragma unroll
    for (int k = 0; k < 4; k++) {
        int i = base + k;
        if (i < NN) s += d_cnt[i] + 1;
    }
    sh[tid] = s; __syncthreads();
    for (int o = 128; o; o >>= 1) { if (tid < o) sh[tid] += sh[tid + o]; __syncthreads(); }
    if (tid == 0) d_bsum[b] = sh[0];
}

// ---------------- K3b: exclusive scan of block sums ----------------
__global__ void k_scan2() {
    __shared__ int sh[NBLK];
    int tid = threadIdx.x;
    if (tid < NBLK) sh[tid] = d_bsum[tid];
    __syncthreads();
    if (tid == 0) {
        int run = 0;
        for (int i = 0; i < NBLK; i++) { int v = sh[i]; sh[i] = run; run += v; }
    }
    __syncthreads();
    if (tid < NBLK) d_bbase[tid] = sh[tid];
}

// ---------------- K3c: intra-block exclusive scan -> offsets + cursors ----------------
__global__ void k_scan3() {
    __shared__ int tsum[256];
    int b = blockIdx.x, tid = threadIdx.x;
    int base = b * 1024 + tid * 4;
    int loc[4]; int s = 0;
#pragma unroll
    for (int k = 0; k < 4; k++) {
        int i = base + k;
        int v = (i < NN) ? (d_cnt[i] + 1) : 0;
        loc[k] = s; s += v;
    }
    tsum[tid] = s; __syncthreads();
    for (int o = 1; o < 256; o <<= 1) {
        int y = (tid >= o) ? tsum[tid - o] : 0;
        __syncthreads();
        tsum[tid] += y;
        __syncthreads();
    }
    int start = d_bbase[b] + tsum[tid] - s;   // exclusive
#pragma unroll
    for (int k = 0; k < 4; k++) {
        int i = base + k;
        if (i < NN) { int o = start + loc[k]; d_off[i] = o; d_cur[i] = o; }
    }
}

// ---------------- K4: bucket edges (+self) into CSR ----------------
__global__ void k_bucket(const int* __restrict__ ei) {
    int g = blockIdx.x * blockDim.x + threadIdx.x;
    if (g < NE) {
        int r = ei[g];
        int c = ei[NE + g];
        int pos = atomicAdd(&d_cur[c], 1);
        d_src[pos] = r;
    } else if (g < NE + NN) {
        int i = g - NE;
        int pos = atomicAdd(&d_cur[i], 1);
        d_src[pos] = i;                       // self loop
    }
}

// ---------------- K5: layer-1 gather + W1 GEMM + relu, store h1s fp16 ----------------
__global__ void k_aggx_h1(const float* __restrict__ W1, const float* __restrict__ b1) {
    __shared__ float W1s[FXD][H];
    __shared__ float b1s[H];
    int tid = threadIdx.x;                    // 256
    if (tid < FXD * H) W1s[tid >> 6][tid & 63] = W1[tid];
    if (tid < H) b1s[tid] = b1[tid];
    __syncthreads();

    int i = blockIdx.x * 8 + (tid >> 5);      // node, 12500 blocks
    int lane = tid & 31;
    int off = d_off[i];
    int cnt = d_cnt[i] + 1;
    float4 acc = make_float4(0.f, 0.f, 0.f, 0.f);
    for (int j = lane; j < cnt; j += 32) {
        int r = d_src[off + j];
        float4 t = d_xs[r];
        acc.x += t.x; acc.y += t.y; acc.z += t.z; acc.w += t.w;
    }
#pragma unroll
    for (int o = 16; o; o >>= 1) {
        acc.x += __shfl_xor_sync(0xffffffffu, acc.x, o);
        acc.y += __shfl_xor_sync(0xffffffffu, acc.y, o);
        acc.z += __shfl_xor_sync(0xffffffffu, acc.z, o);
        acc.w += __shfl_xor_sync(0xffffffffu, acc.w, o);
    }
    float di = d_dis[i];
    float4 v = make_float4(di * acc.x, di * acc.y, di * acc.z, di * acc.w);
    int f0 = 2 * lane;
    float h0 = b1s[f0]   + v.x * W1s[0][f0]   + v.y * W1s[1][f0]   + v.z * W1s[2][f0]   + v.w * W1s[3][f0];
    float h1 = b1s[f0+1] + v.x * W1s[0][f0+1] + v.y * W1s[1][f0+1] + v.z * W1s[2][f0+1] + v.w * W1s[3][f0+1];
    h0 = fmaxf(h0, 0.f) * di;
    h1 = fmaxf(h1, 0.f) * di;
    ((__half2*)d_h1s)[i * 32 + lane] = __floats2half2_rn(h0, h1);
}

// ---------------- K6: layer-2 gather (warp per node, coalesced 128B rows) ----------------
__global__ void k_aggh(void) {
    int i = blockIdx.x * 8 + (threadIdx.x >> 5);   // node, 12500 blocks
    int lane = threadIdx.x & 31;
    int off = d_off[i];
    int cnt = d_cnt[i] + 1;
    const __half2* h1s2 = (const __half2*)d_h1s;
    float ax0 = 0.f, ay0 = 0.f, ax1 = 0.f, ay1 = 0.f;
    int t = 0;
    for (; t + 2 <= cnt; t += 2) {
        int r0 = __ldg(&d_src[off + t]);
        int r1 = __ldg(&d_src[off + t + 1]);
        float2 f0 = __half22float2(h1s2[r0 * 32 + lane]);
        float2 f1 = __half22float2(h1s2[r1 * 32 + lane]);
        ax0 += f0.x; ay0 += f0.y;
        ax1 += f1.x; ay1 += f1.y;
    }
    if (t < cnt) {
        int r0 = __ldg(&d_src[off + t]);
        float2 f0 = __half22float2(h1s2[r0 * 32 + lane]);
        ax0 += f0.x; ay0 += f0.y;
    }
    float di = d_dis[i];
    ((float2*)d_v)[i * 32 + lane] = make_float2(di * (ax0 + ax1), di * (ay0 + ay1));
}

// ---------------- K7: h2 = relu(v @ W2 + b2), fused max-pool (f32x2) ----------------
__global__ void k_h2pool(const float* __restrict__ W2, const float* __restrict__ b2,
                         const int* __restrict__ batch) {
    __shared__ __align__(16) float vt[H][12];   // [k][node], 8 nodes + pad
    int i0 = blockIdx.x * 8;                    // 12500 blocks
    int tid = threadIdx.x;                      // 128
    for (int idx = tid; idx < 8 * H; idx += 128) {
        int n = idx >> 6, k = idx & 63;
        vt[k][n] = d_v[(i0 + n) * H + k];
    }
    __syncthreads();

    int f = tid;
    float bb = b2[f];
    unsigned long long a01 = pack2(bb, bb), a23 = a01, a45 = a01, a67 = a01;
#pragma unroll
    for (int k = 0; k < H; k++) {
        float wv = W2[k * H2 + f];
        unsigned long long wd = pack2(wv, wv);
        ulonglong2 P = *(const ulonglong2*)&vt[k][0];
        ulonglong2 Q = *(const ulonglong2*)&vt[k][4];
        a01 = fma2(P.x, wd, a01);
        a23 = fma2(P.y, wd, a23);
        a45 = fma2(Q.x, wd, a45);
        a67 = fma2(Q.y, wd, a67);
    }
    float2 r01 = unpack2(a01), r23 = unpack2(a23), r45 = unpack2(a45), r67 = unpack2(a67);
    float h[8] = { r01.x, r01.y, r23.x, r23.y, r45.x, r45.y, r67.x, r67.y };

    int bA = batch[i0];
    int bB = batch[i0 + 7];
    float mA = -1.f, mB = -1.f;
#pragma unroll
    for (int n = 0; n < 8; n++) {
        float hv = fmaxf(h[n], 0.f);
        if (batch[i0 + n] == bA) mA = fmaxf(mA, hv); else mB = fmaxf(mB, hv);
    }
    atomicMax(&d_gbits[bA * H2 + f], __float_as_int(mA));
    if (bB != bA) atomicMax(&d_gbits[bB * H2 + f], __float_as_int(mB));
}

// ---------------- K8: conv1d branch (packed f32x2 over tap pairs) ----------------
__global__ void k_conv1d(const float* __restrict__ target,
                         const float* __restrict__ Wc, const float* __restrict__ bc) {
    __shared__ __align__(16) float sh[LL][6];   // col 5 = zero pad
    __shared__ float red[256];
    int g = blockIdx.x;
    int tid = threadIdx.x;                      // 256
    const float* tg = target + (size_t)g * LL * FXT;
    for (int idx = tid; idx < LL * FXT; idx += 256) {
        int l = idx / FXT, i = idx - l * FXT;
        sh[l][i] = tg[idx];
    }
    for (int l = tid; l < LL; l += 256) sh[l][5] = 0.f;
    __syncthreads();

    int c   = tid & 63;
    int seg = tid >> 6;
    unsigned long long wk[3][3];
#pragma unroll
    for (int k = 0; k < 3; k++)
#pragma unroll
        for (int p = 0; p < 3; p++) {
            float w0 = Wc[c * 15 + (2 * p) * 3 + k];
            float w1 = (p < 2) ? Wc[c * 15 + (2 * p + 1) * 3 + k] : 0.f;
            wk[k][p] = pack2(w0, w1);
        }

    int start = seg * 250;
    int end = (seg == 3) ? (LL - 2) : (start + 250);
    float m = -3.4e38f;
    for (int l = start; l < end; l++) {
        unsigned long long a0 = 0ull, a1 = 0ull, a2 = 0ull;
#pragma unroll
        for (int k = 0; k < 3; k++) {
            const unsigned long long* row = (const unsigned long long*)&sh[l + k][0];
            a0 = fma2(row[0], wk[k][0], a0);
            a1 = fma2(row[1], wk[k][1], a1);
            a2 = fma2(row[2], wk[k][2], a2);
        }
        float2 f0 = unpack2(a0), f1 = unpack2(a1), f2 = unpack2(a2);
        m = fmaxf(m, (f0.x + f0.y) + (f1.x + f1.y) + (f2.x + f2.y));
    }
    red[tid] = m;
    __syncthreads();
    if (seg == 0) {
        m = fmaxf(fmaxf(red[c], red[64 + c]), fmaxf(red[128 + c], red[192 + c]));
        m += bc[c];
        d_tmax[g * H + c] = fmaxf(m, 0.f);
    }
}

// ---------------- K9: fused final MLPs ----------------
__global__ void k_final(const float* __restrict__ Wg, const float* __restrict__ bg,
                        const float* __restrict__ Wt, const float* __restrict__ bt,
                        const float* __restrict__ Wf, const float* __restrict__ bf,
                        const float* __restrict__ Wo, const float* __restrict__ bo,
                        float* __restrict__ out) {
    __shared__ float sg[H2], st[H], sxc[H2], sy[H];
    int g = blockIdx.x;
    int f = threadIdx.x;                    // 64
    sg[f]      = __int_as_float(d_gbits[g * H2 + f]);
    sg[H + f]  = __int_as_float(d_gbits[g * H2 + H + f]);
    st[f]      = d_tmax[g * H + f];
    __syncthreads();

    float gg = bg[f];
#pragma unroll 8
    for (int j = 0; j < H2; j++) gg += sg[j] * Wg[j * H + f];
    float tt = bt[f];
#pragma unroll 8
    for (int j = 0; j < H; j++) tt += st[j] * Wt[j * H + f];
    sxc[f] = gg;
    sxc[H + f] = tt;
    __syncthreads();

    float y = bf[f];
#pragma unroll 8
    for (int j = 0; j < H2; j++) y += sxc[j] * Wf[j * H + f];
    sy[f] = fmaxf(y, 0.f);
    __syncthreads();

    if (f < NOUT) {
        float o = bo[f];
#pragma unroll 8
        for (int j = 0; j < H; j++) o += sy[j] * Wo[j * NOUT + f];
        out[g * NOUT + f] = o;
    }
}

// ---------------- launch ----------------
extern "C" void kernel_launch(void* const* d_in, const int* in_sizes, int n_in,
                              void* d_out, int out_size) {
    const float* x      = (const float*)d_in[0];
    const int*   ei     = (const int*)d_in[1];
    const int*   batch  = (const int*)d_in[2];
    const float* target = (const float*)d_in[3];
    const float* W1 = (const float*)d_in[4];
    const float* b1 = (const float*)d_in[5];
    const float* W2 = (const float*)d_in[6];
    const float* b2 = (const float*)d_in[7];
    const float* Wg = (const float*)d_in[8];
    const float* bg = (const float*)d_in[9];
    const float* Wc = (const float*)d_in[10];
    const float* bc = (const float*)d_in[11];
    const float* Wt = (const float*)d_in[12];
    const float* bt = (const float*)d_in[13];
    const float* Wf = (const float*)d_in[14];
    const float* bf = (const float*)d_in[15];
    const float* Wo = (const float*)d_in[16];
    const float* bo = (const float*)d_in[17];
    float* out = (float*)d_out;

    k_init<<<512, 256>>>();
    k_hist<<<(NE + 255) / 256, 256>>>(ei);
    k_dis_xs<<<(NN + 255) / 256, 256>>>(x);
    k_scan1<<<NBLK, 256>>>();
    k_scan2<<<1, 128>>>();
    k_scan3<<<NBLK, 256>>>();
    k_bucket<<<(NE + NN + 255) / 256, 256>>>(ei);
    k_aggx_h1<<<NN / 8, 256>>>(W1, b1);
    k_aggh<<<NN / 8, 256>>>();
    k_h2pool<<<NN / 8, 128>>>(W2, b2, batch);
    k_conv1d<<<NG, 256>>>(target, Wc, bc);
    k_final<<<NG, 64>>>(Wg, bg, Wt, bt, Wf, bf, Wo, bo, out);
}

// round 7
// speedup vs baseline: 1.4174x; 1.0137x over previous
#include <cuda_runtime.h>
#include <cuda_fp16.h>
#include <cstdint>

#define NN  100000
#define NE  1600000
#define NG  512
#define LL  1000
#define FXD 4
#define FXT 5
#define H   64
#define H2  128
#define NOUT 2
#define NBLK 98          // ceil(NN/1024) scan blocks
#define GCNB (NN / 8)    // 12500 gcn blocks in fused kernel

// ---------------- scratch ----------------
__device__ int    d_cnt[NN];           // in-degree (edges only; +1 self added logically)
__device__ int    d_off[NN];           // CSR offsets (incl. self)
__device__ int    d_cur[NN];           // bucket cursors
__device__ int    d_bsum[128];
__device__ int    d_bbase[128];
__device__ int    d_src[NE + NN];      // CSR source list (incl. self edge)
__device__ float  d_dis[NN];
__device__ float4 d_xs[NN];            // dis[i] * x[i]
__device__ __half d_h1s[NN * H];       // dis[i] * relu-h1[i], fp16
__device__ int    d_gbits[NG * H2];    // pooled max(h2) as ordered int bits
__device__ float  d_tmax[NG * H];      // conv1d branch pooled output

__device__ __forceinline__ unsigned long long fma2(unsigned long long a,
                                                   unsigned long long b,
                                                   unsigned long long c) {
    unsigned long long d;
    asm("fma.rn.f32x2 %0, %1, %2, %3;" : "=l"(d) : "l"(a), "l"(b), "l"(c));
    return d;
}
__device__ __forceinline__ unsigned long long pack2(float a, float b) {
    unsigned long long d;
    asm("mov.b64 %0, {%1,%2};" : "=l"(d) : "f"(a), "f"(b));
    return d;
}
__device__ __forceinline__ float2 unpack2(unsigned long long a) {
    float2 r;
    asm("mov.b64 {%0,%1}, %2;" : "=f"(r.x), "=f"(r.y) : "l"(a));
    return r;
}

// ---------------- K0: init ----------------
__global__ void k_init() {
    int stride = gridDim.x * blockDim.x;
    int tid = blockIdx.x * blockDim.x + threadIdx.x;
    for (int i = tid; i < NN; i += stride) d_cnt[i] = 0;
    for (int i = tid; i < NG * H2; i += stride) d_gbits[i] = 0;   // relu>=0
}

// ---------------- K1: in-degree histogram ----------------
__global__ void k_hist(const int* __restrict__ ei) {
    int e = blockIdx.x * blockDim.x + threadIdx.x;
    if (e < NE) atomicAdd(&d_cnt[ei[NE + e]], 1);
}

// ---------------- K2a: per-block sums of (cnt+1) ----------------
__global__ void k_scan1() {
    __shared__ int sh[256];
    int b = blockIdx.x, tid = threadIdx.x;
    int base = b * 1024 + tid * 4;
    int s = 0;
#pragma unroll
    for (int k = 0; k < 4; k++) {
        int i = base + k;
        if (i < NN) s += d_cnt[i] + 1;
    }
    sh[tid] = s; __syncthreads();
    for (int o = 128; o; o >>= 1) { if (tid < o) sh[tid] += sh[tid + o]; __syncthreads(); }
    if (tid == 0) d_bsum[b] = sh[0];
}

// ---------------- K2b: exclusive scan of block sums ----------------
__global__ void k_scan2() {
    __shared__ int sh[NBLK];
    int tid = threadIdx.x;
    if (tid < NBLK) sh[tid] = d_bsum[tid];
    __syncthreads();
    if (tid == 0) {
        int run = 0;
        for (int i = 0; i < NBLK; i++) { int v = sh[i]; sh[i] = run; run += v; }
    }
    __syncthreads();
    if (tid < NBLK) d_bbase[tid] = sh[tid];
}

// ---------------- K2c: intra-block scan -> offsets + cursors; also dis + xs ----------------
__global__ void k_scan3(const float* __restrict__ x) {
    __shared__ int tsum[256];
    int b = blockIdx.x, tid = threadIdx.x;
    int base = b * 1024 + tid * 4;
    int loc[4]; int s = 0;
#pragma unroll
    for (int k = 0; k < 4; k++) {
        int i = base + k;
        int v = (i < NN) ? (d_cnt[i] + 1) : 0;
        loc[k] = s; s += v;
    }
    tsum[tid] = s; __syncthreads();
    for (int o = 1; o < 256; o <<= 1) {
        int y = (tid >= o) ? tsum[tid - o] : 0;
        __syncthreads();
        tsum[tid] += y;
        __syncthreads();
    }
    int start = d_bbase[b] + tsum[tid] - s;   // exclusive
#pragma unroll
    for (int k = 0; k < 4; k++) {
        int i = base + k;
        if (i < NN) {
            int o = start + loc[k];
            d_off[i] = o; d_cur[i] = o;
            float di = rsqrtf((float)(d_cnt[i] + 1));
            d_dis[i] = di;
            float4 xv = ((const float4*)x)[i];
            d_xs[i] = make_float4(di * xv.x, di * xv.y, di * xv.z, di * xv.w);
        }
    }
}

// ---------------- K3: bucket edges (+self) into CSR ----------------
__global__ void k_bucket(const int* __restrict__ ei) {
    int g = blockIdx.x * blockDim.x + threadIdx.x;
    if (g < NE) {
        int r = ei[g];
        int c = ei[NE + g];
        int pos = atomicAdd(&d_cur[c], 1);
        d_src[pos] = r;
    } else if (g < NE + NN) {
        int i = g - NE;
        int pos = atomicAdd(&d_cur[i], 1);
        d_src[pos] = i;                       // self loop
    }
}

// ---------------- K4: layer-1 gather + W1 GEMM + relu, store h1s fp16 ----------------
__global__ void k_aggx_h1(const float* __restrict__ W1, const float* __restrict__ b1) {
    __shared__ float W1s[FXD][H];
    __shared__ float b1s[H];
    int tid = threadIdx.x;                    // 256
    if (tid < FXD * H) W1s[tid >> 6][tid & 63] = W1[tid];
    if (tid < H) b1s[tid] = b1[tid];
    __syncthreads();

    int i = blockIdx.x * 8 + (tid >> 5);      // node
    int lane = tid & 31;
    int off = d_off[i];
    int cnt = d_cnt[i] + 1;
    float4 acc = make_float4(0.f, 0.f, 0.f, 0.f);
    for (int j = lane; j < cnt; j += 32) {
        int r = d_src[off + j];
        float4 t = d_xs[r];
        acc.x += t.x; acc.y += t.y; acc.z += t.z; acc.w += t.w;
    }
#pragma unroll
    for (int o = 16; o; o >>= 1) {
        acc.x += __shfl_xor_sync(0xffffffffu, acc.x, o);
        acc.y += __shfl_xor_sync(0xffffffffu, acc.y, o);
        acc.z += __shfl_xor_sync(0xffffffffu, acc.z, o);
        acc.w += __shfl_xor_sync(0xffffffffu, acc.w, o);
    }
    float di = d_dis[i];
    float4 v = make_float4(di * acc.x, di * acc.y, di * acc.z, di * acc.w);
    int f0 = 2 * lane;
    float h0 = b1s[f0]   + v.x * W1s[0][f0]   + v.y * W1s[1][f0]   + v.z * W1s[2][f0]   + v.w * W1s[3][f0];
    float h1 = b1s[f0+1] + v.x * W1s[0][f0+1] + v.y * W1s[1][f0+1] + v.z * W1s[2][f0+1] + v.w * W1s[3][f0+1];
    h0 = fmaxf(h0, 0.f) * di;
    h1 = fmaxf(h1, 0.f) * di;
    ((__half2*)d_h1s)[i * 32 + lane] = __floats2half2_rn(h0, h1);
}

// ---------------- K5 fused: blocks [0,NG) conv1d branch; blocks [NG, NG+GCNB) aggh+h2pool ----
__global__ void k_fused(const float* __restrict__ W2, const float* __restrict__ b2,
                        const int* __restrict__ batch,
                        const float* __restrict__ target,
                        const float* __restrict__ Wc, const float* __restrict__ bc) {
    __shared__ __align__(16) char s_raw[25088];
    int tid = threadIdx.x;                    // 256

    if (blockIdx.x < NG) {
        // ---------------- conv1d branch ----------------
        float (*sh)[6] = (float(*)[6])s_raw;          // [LL][6], col 5 = zero pad
        float* red = (float*)(s_raw + 24000);         // [256]
        int g = blockIdx.x;
        const float* tg = target + (size_t)g * LL * FXT;
        for (int idx = tid; idx < LL * FXT; idx += 256) {
            int l = idx / FXT, i = idx - l * FXT;
            sh[l][i] = tg[idx];
        }
        for (int l = tid; l < LL; l += 256) sh[l][5] = 0.f;
        __syncthreads();

        int c   = tid & 63;
        int seg = tid >> 6;
        unsigned long long wk[3][3];
#pragma unroll
        for (int k = 0; k < 3; k++)
#pragma unroll
            for (int p = 0; p < 3; p++) {
                float w0 = Wc[c * 15 + (2 * p) * 3 + k];
                float w1 = (p < 2) ? Wc[c * 15 + (2 * p + 1) * 3 + k] : 0.f;
                wk[k][p] = pack2(w0, w1);
            }

        int start = seg * 250;
        int end = (seg == 3) ? (LL - 2) : (start + 250);
        float m = -3.4e38f;
        for (int l = start; l < end; l++) {
            unsigned long long a0 = 0ull, a1 = 0ull, a2 = 0ull;
#pragma unroll
            for (int k = 0; k < 3; k++) {
                const unsigned long long* row = (const unsigned long long*)&sh[l + k][0];
                a0 = fma2(row[0], wk[k][0], a0);
                a1 = fma2(row[1], wk[k][1], a1);
                a2 = fma2(row[2], wk[k][2], a2);
            }
            float2 f0 = unpack2(a0), f1 = unpack2(a1), f2 = unpack2(a2);
            m = fmaxf(m, (f0.x + f0.y) + (f1.x + f1.y) + (f2.x + f2.y));
        }
        red[tid] = m;
        __syncthreads();
        if (seg == 0) {
            m = fmaxf(fmaxf(red[c], red[64 + c]), fmaxf(red[128 + c], red[192 + c]));
            m += bc[c];
            d_tmax[g * H + c] = fmaxf(m, 0.f);
        }
        return;
    }

    // ---------------- layer-2 gather + W2 GEMM + pooled max ----------------
    float (*vt)[12] = (float(*)[12])s_raw;    // [H][12], 8 nodes + pad
    int i0 = (blockIdx.x - NG) * 8;

    {   // phase 1: warp per node
        int w = tid >> 5;
        int lane = tid & 31;
        int i = i0 + w;
        int off = d_off[i];
        int cnt = d_cnt[i] + 1;
        const __half2* h1s2 = (const __half2*)d_h1s;
        float ax0 = 0.f, ay0 = 0.f, ax1 = 0.f, ay1 = 0.f;
        int t = 0;
        for (; t + 2 <= cnt; t += 2) {
            int r0 = __ldg(&d_src[off + t]);
            int r1 = __ldg(&d_src[off + t + 1]);
            float2 f0 = __half22float2(h1s2[r0 * 32 + lane]);
            float2 f1 = __half22float2(h1s2[r1 * 32 + lane]);
            ax0 += f0.x; ay0 += f0.y;
            ax1 += f1.x; ay1 += f1.y;
        }
        if (t < cnt) {
            int r0 = __ldg(&d_src[off + t]);
            float2 f0 = __half22float2(h1s2[r0 * 32 + lane]);
            ax0 += f0.x; ay0 += f0.y;
        }
        float di = d_dis[i];
        vt[2 * lane][w]     = di * (ax0 + ax1);
        vt[2 * lane + 1][w] = di * (ay0 + ay1);
    }
    __syncthreads();

    // phase 2: GEMM, 256 threads: f = tid&127, half = tid>>7 handles 4 nodes
    int f = tid & 127;
    int half = tid >> 7;
    float bb = b2[f];
    unsigned long long a01 = pack2(bb, bb), a23 = a01;
#pragma unroll
    for (int k = 0; k < H; k++) {
        float wv = __ldg(&W2[k * H2 + f]);
        unsigned long long wd = pack2(wv, wv);
        ulonglong2 P = *(const ulonglong2*)&vt[k][half * 4];
        a01 = fma2(P.x, wd, a01);
        a23 = fma2(P.y, wd, a23);
    }
    float2 r01 = unpack2(a01), r23 = unpack2(a23);
    float h[4] = { r01.x, r01.y, r23.x, r23.y };

    int bA = batch[i0];
    int bB = batch[i0 + 7];
    float mA = -1.f, mB = -1.f;
#pragma unroll
    for (int n = 0; n < 4; n++) {
        float hv = fmaxf(h[n], 0.f);
        if (batch[i0 + half * 4 + n] == bA) mA = fmaxf(mA, hv); else mB = fmaxf(mB, hv);
    }
    atomicMax(&d_gbits[bA * H2 + f], __float_as_int(mA));   // mA=-1 sentinel: no-op vs >=0
    if (bB != bA) atomicMax(&d_gbits[bB * H2 + f], __float_as_int(mB));
}

// ---------------- K6: fused final MLPs ----------------
__global__ void k_final(const float* __restrict__ Wg, const float* __restrict__ bg,
                        const float* __restrict__ Wt, const float* __restrict__ bt,
                        const float* __restrict__ Wf, const float* __restrict__ bf,
                        const float* __restrict__ Wo, const float* __restrict__ bo,
                        float* __restrict__ out) {
    __shared__ float sg[H2], st[H], sxc[H2], sy[H];
    int g = blockIdx.x;
    int f = threadIdx.x;                    // 64
    sg[f]      = __int_as_float(d_gbits[g * H2 + f]);
    sg[H + f]  = __int_as_float(d_gbits[g * H2 + H + f]);
    st[f]      = d_tmax[g * H + f];
    __syncthreads();

    float gg = bg[f];
#pragma unroll 8
    for (int j = 0; j < H2; j++) gg += sg[j] * Wg[j * H + f];
    float tt = bt[f];
#pragma unroll 8
    for (int j = 0; j < H; j++) tt += st[j] * Wt[j * H + f];
    sxc[f] = gg;
    sxc[H + f] = tt;
    __syncthreads();

    float y = bf[f];
#pragma unroll 8
    for (int j = 0; j < H2; j++) y += sxc[j] * Wf[j * H + f];
    sy[f] = fmaxf(y, 0.f);
    __syncthreads();

    if (f < NOUT) {
        float o = bo[f];
#pragma unroll 8
        for (int j = 0; j < H; j++) o += sy[j] * Wo[j * NOUT + f];
        out[g * NOUT + f] = o;
    }
}

// ---------------- launch ----------------
extern "C" void kernel_launch(void* const* d_in, const int* in_sizes, int n_in,
                              void* d_out, int out_size) {
    const float* x      = (const float*)d_in[0];
    const int*   ei     = (const int*)d_in[1];
    const int*   batch  = (const int*)d_in[2];
    const float* target = (const float*)d_in[3];
    const float* W1 = (const float*)d_in[4];
    const float* b1 = (const float*)d_in[5];
    const float* W2 = (const float*)d_in[6];
    const float* b2 = (const float*)d_in[7];
    const float* Wg = (const float*)d_in[8];
    const float* bg = (const float*)d_in[9];
    const float* Wc = (const float*)d_in[10];
    const float* bc = (const float*)d_in[11];
    const float* Wt = (const float*)d_in[12];
    const float* bt = (const float*)d_in[13];
    const float* Wf = (const float*)d_in[14];
    const float* bf = (const float*)d_in[15];
    const float* Wo = (const float*)d_in[16];
    const float* bo = (const float*)d_in[17];
    float* out = (float*)d_out;

    k_init<<<512, 256>>>();
    k_hist<<<(NE + 255) / 256, 256>>>(ei);
    k_scan1<<<NBLK, 256>>>();
    k_scan2<<<1, 128>>>();
    k_scan3<<<NBLK, 256>>>(x);
    k_bucket<<<(NE + NN + 255) / 256, 256>>>(ei);
    k_aggx_h1<<<NN / 8, 256>>>(W1, b1);
    k_fused<<<NG + GCNB, 256>>>(W2, b2, batch, target, Wc, bc);
    k_final<<<NG, 64>>>(Wg, bg, Wt, bt, Wf, bf, Wo, bo, out);
}

// round 8
// speedup vs baseline: 1.5437x; 1.0891x over previous
#include <cuda_runtime.h>
#include <cuda_fp16.h>
#include <cstdint>

#define NN  100000
#define NE  1600000
#define NG  512
#define LL  1000
#define FXD 4
#define FXT 5
#define H   64
#define H2  128
#define NOUT 2
#define NBLK 98          // ceil(NN/1024) scan blocks
#define HISTB ((NE + 1023) / 1024)   // 1563 hist blocks (4 edges/thread)

// ---------------- scratch (zero at load; k_final re-zeroes what must be zero) ----------------
__device__ int    d_cnt[NN];           // in-degree (edges only; +1 self added logically)
__device__ int    d_off[NN];           // CSR offsets (incl. self)
__device__ int    d_cur[NN];           // bucket cursors
__device__ int    d_bsum[128];
__device__ int    d_bbase[128];
__device__ int    d_scan_done;
__device__ int    d_src[NE + NN];      // CSR source list (self at off[i], edges after)
__device__ float  d_dis[NN];
__device__ float4 d_xs[NN];            // dis[i] * x[i]
__device__ __half d_h1s[NN * H];       // dis[i] * relu-h1[i], fp16
__device__ int    d_gbits[NG * H2];    // pooled max(h2) as ordered int bits
__device__ float  d_tmax[NG * H];      // conv1d branch pooled output

__device__ __forceinline__ unsigned long long fma2(unsigned long long a,
                                                   unsigned long long b,
                                                   unsigned long long c) {
    unsigned long long d;
    asm("fma.rn.f32x2 %0, %1, %2, %3;" : "=l"(d) : "l"(a), "l"(b), "l"(c));
    return d;
}
__device__ __forceinline__ unsigned long long pack2(float a, float b) {
    unsigned long long d;
    asm("mov.b64 %0, {%1,%2};" : "=l"(d) : "f"(a), "f"(b));
    return d;
}
__device__ __forceinline__ float2 unpack2(unsigned long long a) {
    float2 r;
    asm("mov.b64 {%0,%1}, %2;" : "=f"(r.x), "=f"(r.y) : "l"(a));
    return r;
}

// ---------------- K1: blocks [0,NG): conv1d branch; blocks [NG,...): degree histogram ----
__global__ void k_histconv(const int* __restrict__ ei,
                           const float* __restrict__ target,
                           const float* __restrict__ Wc, const float* __restrict__ bc) {
    __shared__ __align__(16) char s_raw[25088];
    int tid = threadIdx.x;                    // 256

    if (blockIdx.x >= NG) {
        // ---- histogram: 4 edges per thread over the col half of ei ----
        int e = (blockIdx.x - NG) * 1024 + tid * 4;
        if (e + 4 <= NE) {
            int4 c4 = *(const int4*)(ei + NE + e);
            atomicAdd(&d_cnt[c4.x], 1);
            atomicAdd(&d_cnt[c4.y], 1);
            atomicAdd(&d_cnt[c4.z], 1);
            atomicAdd(&d_cnt[c4.w], 1);
        } else {
            for (int k = 0; k < 4 && e + k < NE; k++)
                atomicAdd(&d_cnt[ei[NE + e + k]], 1);
        }
        return;
    }

    // ---- conv1d branch ----
    float (*sh)[6] = (float(*)[6])s_raw;          // [LL][6], col 5 = zero pad
    float* red = (float*)(s_raw + 24000);         // [256]
    int g = blockIdx.x;
    const float* tg = target + (size_t)g * LL * FXT;
    for (int idx = tid; idx < LL * FXT; idx += 256) {
        int l = idx / FXT, i = idx - l * FXT;
        sh[l][i] = tg[idx];
    }
    for (int l = tid; l < LL; l += 256) sh[l][5] = 0.f;
    __syncthreads();

    int c   = tid & 63;
    int seg = tid >> 6;
    unsigned long long wk[3][3];
#pragma unroll
    for (int k = 0; k < 3; k++)
#pragma unroll
        for (int p = 0; p < 3; p++) {
            float w0 = Wc[c * 15 + (2 * p) * 3 + k];
            float w1 = (p < 2) ? Wc[c * 15 + (2 * p + 1) * 3 + k] : 0.f;
            wk[k][p] = pack2(w0, w1);
        }

    int start = seg * 250;
    int end = (seg == 3) ? (LL - 2) : (start + 250);
    float m = -3.4e38f;
    for (int l = start; l < end; l++) {
        unsigned long long a0 = 0ull, a1 = 0ull, a2 = 0ull;
#pragma unroll
        for (int k = 0; k < 3; k++) {
            const unsigned long long* row = (const unsigned long long*)&sh[l + k][0];
            a0 = fma2(row[0], wk[k][0], a0);
            a1 = fma2(row[1], wk[k][1], a1);
            a2 = fma2(row[2], wk[k][2], a2);
        }
        float2 f0 = unpack2(a0), f1 = unpack2(a1), f2 = unpack2(a2);
        m = fmaxf(m, (f0.x + f0.y) + (f1.x + f1.y) + (f2.x + f2.y));
    }
    red[tid] = m;
    __syncthreads();
    if (seg == 0) {
        m = fmaxf(fmaxf(red[c], red[64 + c]), fmaxf(red[128 + c], red[192 + c]));
        m += bc[c];
        d_tmax[g * H + c] = fmaxf(m, 0.f);
    }
}

// ---------------- K2: per-block sums + last-block scan of block sums ----------------
__global__ void k_scan12() {
    __shared__ int sh[256];
    __shared__ int lastflag;
    int b = blockIdx.x, tid = threadIdx.x;
    int base = b * 1024 + tid * 4;
    int s = 0;
#pragma unroll
    for (int k = 0; k < 4; k++) {
        int i = base + k;
        if (i < NN) s += d_cnt[i] + 1;
    }
    sh[tid] = s; __syncthreads();
    for (int o = 128; o; o >>= 1) { if (tid < o) sh[tid] += sh[tid + o]; __syncthreads(); }
    if (tid == 0) {
        d_bsum[b] = sh[0];
        __threadfence();
        int t = atomicAdd(&d_scan_done, 1);
        lastflag = (t == NBLK - 1);
    }
    __syncthreads();
    if (lastflag) {
        __threadfence();
        int v = (tid < NBLK) ? d_bsum[tid] : 0;
        sh[tid] = v; __syncthreads();
        for (int o = 1; o < 256; o <<= 1) {
            int y = (tid >= o) ? sh[tid - o] : 0;
            __syncthreads();
            sh[tid] += y;
            __syncthreads();
        }
        if (tid < NBLK) d_bbase[tid] = sh[tid] - v;   // exclusive
        if (tid == 0) d_scan_done = 0;
    }
}

// ---------------- K3: intra-block scan -> offsets, cursors(off+1), self entry, dis, xs ----
__global__ void k_scan3(const float* __restrict__ x) {
    __shared__ int tsum[256];
    int b = blockIdx.x, tid = threadIdx.x;
    int base = b * 1024 + tid * 4;
    int loc[4]; int s = 0;
#pragma unroll
    for (int k = 0; k < 4; k++) {
        int i = base + k;
        int v = (i < NN) ? (d_cnt[i] + 1) : 0;
        loc[k] = s; s += v;
    }
    tsum[tid] = s; __syncthreads();
    for (int o = 1; o < 256; o <<= 1) {
        int y = (tid >= o) ? tsum[tid - o] : 0;
        __syncthreads();
        tsum[tid] += y;
        __syncthreads();
    }
    int start = d_bbase[b] + tsum[tid] - s;   // exclusive
#pragma unroll
    for (int k = 0; k < 4; k++) {
        int i = base + k;
        if (i < NN) {
            int o = start + loc[k];
            d_off[i] = o;
            d_cur[i] = o + 1;                 // edges go after the self entry
            d_src[o] = i;                     // self loop
            float di = rsqrtf((float)(d_cnt[i] + 1));
            d_dis[i] = di;
            float4 xv = ((const float4*)x)[i];
            d_xs[i] = make_float4(di * xv.x, di * xv.y, di * xv.z, di * xv.w);
        }
    }
}

// ---------------- K4: bucket edges into CSR ----------------
__global__ void k_bucket(const int* __restrict__ ei) {
    int e = blockIdx.x * blockDim.x + threadIdx.x;
    if (e >= NE) return;
    int r = ei[e];
    int c = ei[NE + e];
    int pos = atomicAdd(&d_cur[c], 1);
    d_src[pos] = r;
}

// ---------------- K5: layer-1 gather + W1 GEMM + relu, store h1s fp16 ----------------
__global__ void k_aggx_h1(const float* __restrict__ W1, const float* __restrict__ b1) {
    __shared__ float W1s[FXD][H];
    __shared__ float b1s[H];
    int tid = threadIdx.x;                    // 256
    if (tid < FXD * H) W1s[tid >> 6][tid & 63] = W1[tid];
    if (tid < H) b1s[tid] = b1[tid];
    __syncthreads();

    int i = blockIdx.x * 8 + (tid >> 5);      // node
    int lane = tid & 31;
    int off = d_off[i];
    int cnt = d_cnt[i] + 1;
    float4 acc = make_float4(0.f, 0.f, 0.f, 0.f);
    for (int j = lane; j < cnt; j += 32) {
        int r = d_src[off + j];
        float4 t = d_xs[r];
        acc.x += t.x; acc.y += t.y; acc.z += t.z; acc.w += t.w;
    }
#pragma unroll
    for (int o = 16; o; o >>= 1) {
        acc.x += __shfl_xor_sync(0xffffffffu, acc.x, o);
        acc.y += __shfl_xor_sync(0xffffffffu, acc.y, o);
        acc.z += __shfl_xor_sync(0xffffffffu, acc.z, o);
        acc.w += __shfl_xor_sync(0xffffffffu, acc.w, o);
    }
    float di = d_dis[i];
    float4 v = make_float4(di * acc.x, di * acc.y, di * acc.z, di * acc.w);
    int f0 = 2 * lane;
    float h0 = b1s[f0]   + v.x * W1s[0][f0]   + v.y * W1s[1][f0]   + v.z * W1s[2][f0]   + v.w * W1s[3][f0];
    float h1 = b1s[f0+1] + v.x * W1s[0][f0+1] + v.y * W1s[1][f0+1] + v.z * W1s[2][f0+1] + v.w * W1s[3][f0+1];
    h0 = fmaxf(h0, 0.f) * di;
    h1 = fmaxf(h1, 0.f) * di;
    ((__half2*)d_h1s)[i * 32 + lane] = __floats2half2_rn(h0, h1);
}

// ---------------- K6: layer-2 gather + W2 GEMM + pooled max (16 nodes/block) ----------
__global__ void k_fused(const float* __restrict__ W2, const float* __restrict__ b2,
                        const int* __restrict__ batch) {
    __shared__ __align__(16) float vt[H][20];   // [k][node], 16 nodes + pad (80B rows)
    int tid = threadIdx.x;                      // 256
    int i0 = blockIdx.x * 16;                   // 6250 blocks

    {   // phase 1: warp per 2 nodes
        int w = tid >> 5;
        int lane = tid & 31;
        const __half2* h1s2 = (const __half2*)d_h1s;
#pragma unroll
        for (int sub = 0; sub < 2; sub++) {
            int n = w * 2 + sub;
            int i = i0 + n;
            int off = d_off[i];
            int cnt = d_cnt[i] + 1;
            float ax0 = 0.f, ay0 = 0.f, ax1 = 0.f, ay1 = 0.f;
            int t = 0;
            for (; t + 2 <= cnt; t += 2) {
                int r0 = __ldg(&d_src[off + t]);
                int r1 = __ldg(&d_src[off + t + 1]);
                float2 f0 = __half22float2(h1s2[r0 * 32 + lane]);
                float2 f1 = __half22float2(h1s2[r1 * 32 + lane]);
                ax0 += f0.x; ay0 += f0.y;
                ax1 += f1.x; ay1 += f1.y;
            }
            if (t < cnt) {
                int r0 = __ldg(&d_src[off + t]);
                float2 f0 = __half22float2(h1s2[r0 * 32 + lane]);
                ax0 += f0.x; ay0 += f0.y;
            }
            float di = d_dis[i];
            vt[2 * lane][n]     = di * (ax0 + ax1);
            vt[2 * lane + 1][n] = di * (ay0 + ay1);
        }
    }
    __syncthreads();

    // phase 2: GEMM, f = tid&127, half = tid>>7 handles 8 nodes
    int f = tid & 127;
    int half = tid >> 7;
    float bb = b2[f];
    unsigned long long a01 = pack2(bb, bb), a23 = a01, a45 = a01, a67 = a01;
#pragma unroll
    for (int k = 0; k < H; k++) {
        float wv = __ldg(&W2[k * H2 + f]);
        unsigned long long wd = pack2(wv, wv);
        const ulonglong2* P = (const ulonglong2*)&vt[k][half * 8];
        ulonglong2 p0 = P[0];
        ulonglong2 p1 = P[1];
        a01 = fma2(p0.x, wd, a01);
        a23 = fma2(p0.y, wd, a23);
        a45 = fma2(p1.x, wd, a45);
        a67 = fma2(p1.y, wd, a67);
    }
    float2 r01 = unpack2(a01), r23 = unpack2(a23), r45 = unpack2(a45), r67 = unpack2(a67);
    float h[8] = { r01.x, r01.y, r23.x, r23.y, r45.x, r45.y, r67.x, r67.y };

    int bA = batch[i0];
    int bB = batch[i0 + 15];
    float mA = -1.f, mB = -1.f;
#pragma unroll
    for (int n = 0; n < 8; n++) {
        float hv = fmaxf(h[n], 0.f);
        if (batch[i0 + half * 8 + n] == bA) mA = fmaxf(mA, hv); else mB = fmaxf(mB, hv);
    }
    atomicMax(&d_gbits[bA * H2 + f], __float_as_int(mA));   // -1 bits are negative: no-op
    if (bB != bA) atomicMax(&d_gbits[bB * H2 + f], __float_as_int(mB));
}

// ---------------- K7: fused final MLPs + scratch re-zero for graph replay ----------------
__global__ void k_final(const float* __restrict__ Wg, const float* __restrict__ bg,
                        const float* __restrict__ Wt, const float* __restrict__ bt,
                        const float* __restrict__ Wf, const float* __restrict__ bf,
                        const float* __restrict__ Wo, const float* __restrict__ bo,
                        float* __restrict__ out) {
    __shared__ float sg[H2], st[H], sxc[H2], sy[H];
    int g = blockIdx.x;
    int f = threadIdx.x;                    // 64
    sg[f]      = __int_as_float(d_gbits[g * H2 + f]);
    sg[H + f]  = __int_as_float(d_gbits[g * H2 + H + f]);
    st[f]      = d_tmax[g * H + f];
    // re-zero own gbits slice for next replay (only this block reads it)
    d_gbits[g * H2 + f] = 0;
    d_gbits[g * H2 + H + f] = 0;
    // re-zero d_cnt strided (no kernel after this one reads it)
    for (int i = g * 64 + f; i < NN; i += NG * 64) d_cnt[i] = 0;
    __syncthreads();

    float gg = bg[f];
#pragma unroll 8
    for (int j = 0; j < H2; j++) gg += sg[j] * Wg[j * H + f];
    float tt = bt[f];
#pragma unroll 8
    for (int j = 0; j < H; j++) tt += st[j] * Wt[j * H + f];
    sxc[f] = gg;
    sxc[H + f] = tt;
    __syncthreads();

    float y = bf[f];
#pragma unroll 8
    for (int j = 0; j < H2; j++) y += sxc[j] * Wf[j * H + f];
    sy[f] = fmaxf(y, 0.f);
    __syncthreads();

    if (f < NOUT) {
        float o = bo[f];
#pragma unroll 8
        for (int j = 0; j < H; j++) o += sy[j] * Wo[j * NOUT + f];
        out[g * NOUT + f] = o;
    }
}

// ---------------- launch ----------------
extern "C" void kernel_launch(void* const* d_in, const int* in_sizes, int n_in,
                              void* d_out, int out_size) {
    const float* x      = (const float*)d_in[0];
    const int*   ei     = (const int*)d_in[1];
    const int*   batch  = (const int*)d_in[2];
    const float* target = (const float*)d_in[3];
    const float* W1 = (const float*)d_in[4];
    const float* b1 = (const float*)d_in[5];
    const float* W2 = (const float*)d_in[6];
    const float* b2 = (const float*)d_in[7];
    const float* Wg = (const float*)d_in[8];
    const float* bg = (const float*)d_in[9];
    const float* Wc = (const float*)d_in[10];
    const float* bc = (const float*)d_in[11];
    const float* Wt = (const float*)d_in[12];
    const float* bt = (const float*)d_in[13];
    const float* Wf = (const float*)d_in[14];
    const float* bf = (const float*)d_in[15];
    const float* Wo = (const float*)d_in[16];
    const float* bo = (const float*)d_in[17];
    float* out = (float*)d_out;

    k_histconv<<<NG + HISTB, 256>>>(ei, target, Wc, bc);
    k_scan12<<<NBLK, 256>>>();
    k_scan3<<<NBLK, 256>>>(x);
    k_bucket<<<(NE + 255) / 256, 256>>>(ei);
    k_aggx_h1<<<NN / 8, 256>>>(W1, b1);
    k_fused<<<NN / 16, 256>>>(W2, b2, batch);
    k_final<<<NG, 64>>>(Wg, bg, Wt, bt, Wf, bf, Wo, bo, out);
}